// round 1
// baseline (speedup 1.0000x reference)
#include <cuda_runtime.h>
#include <math.h>

#define D_MODEL 2048
#define SEQ     2048
#define N_HEADS 16
#define HEAD_DIM 128

// Scratch (no cudaMalloc allowed) — 4 x 16 MB
__device__ float g_Q[SEQ * D_MODEL];
__device__ float g_K[SEQ * D_MODEL];
__device__ float g_V[SEQ * D_MODEL];
__device__ float g_A[SEQ * D_MODEL];

// ---------------------------------------------------------------------------
// SGEMM: C[2048,2048] = A[2048,2048] @ B[2048,2048], all fp32 row-major.
// 128x128 block tile, BK=16, 256 threads, 8x8 per thread.
// ---------------------------------------------------------------------------
__global__ __launch_bounds__(256, 2) void sgemm_kernel(
    const float* __restrict__ A, const float* __restrict__ B,
    float* __restrict__ C)
{
    const int K = D_MODEL, N = D_MODEL;
    __shared__ float As[16][128];   // transposed A tile: As[k][m]
    __shared__ float Bs[16][128];   // Bs[k][n]

    int t  = threadIdx.x;
    int tx = t & 15;
    int ty = t >> 4;
    int row0 = blockIdx.y << 7;
    int col0 = blockIdx.x << 7;

    float acc[8][8];
#pragma unroll
    for (int i = 0; i < 8; i++)
#pragma unroll
        for (int j = 0; j < 8; j++) acc[i][j] = 0.0f;

    for (int k0 = 0; k0 < K; k0 += 16) {
#pragma unroll
        for (int i = 0; i < 2; i++) {
            int lin = t + (i << 8);          // 0..511
            int ar  = lin >> 2;              // 0..127
            int ac4 = lin & 3;               // 0..3
            float4 av = *(const float4*)(A + (size_t)(row0 + ar) * K + k0 + (ac4 << 2));
            As[(ac4 << 2) + 0][ar] = av.x;
            As[(ac4 << 2) + 1][ar] = av.y;
            As[(ac4 << 2) + 2][ar] = av.z;
            As[(ac4 << 2) + 3][ar] = av.w;
            int br  = lin >> 5;              // 0..15
            int bc4 = lin & 31;              // 0..31
            *(float4*)&Bs[br][bc4 << 2] =
                *(const float4*)(B + (size_t)(k0 + br) * N + col0 + (bc4 << 2));
        }
        __syncthreads();

#pragma unroll
        for (int k = 0; k < 16; k++) {
            float a[8], b[8];
            *(float4*)&a[0] = *(const float4*)&As[k][(ty << 3)];
            *(float4*)&a[4] = *(const float4*)&As[k][(ty << 3) + 4];
            *(float4*)&b[0] = *(const float4*)&Bs[k][(tx << 3)];
            *(float4*)&b[4] = *(const float4*)&Bs[k][(tx << 3) + 4];
#pragma unroll
            for (int i = 0; i < 8; i++)
#pragma unroll
                for (int j = 0; j < 8; j++)
                    acc[i][j] += a[i] * b[j];
        }
        __syncthreads();
    }

#pragma unroll
    for (int i = 0; i < 8; i++) {
        float* cp = C + (size_t)(row0 + (ty << 3) + i) * N + col0 + (tx << 3);
        *(float4*)cp       = make_float4(acc[i][0], acc[i][1], acc[i][2], acc[i][3]);
        *(float4*)(cp + 4) = make_float4(acc[i][4], acc[i][5], acc[i][6], acc[i][7]);
    }
}

// ---------------------------------------------------------------------------
// RoPE on Q and K in place. One thread per (pos, pair).
// Column layout within row: h*128 + 2*i / 2*i+1, angle index = i (0..63).
// ---------------------------------------------------------------------------
__global__ __launch_bounds__(256) void rope_kernel(
    float* __restrict__ Q, float* __restrict__ K,
    const float* __restrict__ fc, const float* __restrict__ fs)
{
    int idx = blockIdx.x * blockDim.x + threadIdx.x;   // 0 .. SEQ*1024-1
    int s = idx >> 10;         // / (D_MODEL/2)
    int p = idx & 1023;        // pair index within row
    int i = p & 63;            // angle index within head
    float c  = fc[(s << 6) + i];
    float sn = fs[(s << 6) + i];
    size_t base = ((size_t)s << 11) + ((size_t)p << 1);

    float2 q = *(float2*)(Q + base);
    float2 k = *(float2*)(K + base);
    *(float2*)(Q + base) = make_float2(q.x * c - q.y * sn, q.x * sn + q.y * c);
    *(float2*)(K + base) = make_float2(k.x * c - k.y * sn, k.x * sn + k.y * c);
}

// ---------------------------------------------------------------------------
// Flash-style causal attention, fp32.
// Grid: (SEQ/64, N_HEADS). Block: 256 threads.
// Per block: one 64-row Q tile of one head; loop over 64-key tiles (causal).
// Smem: Qs[64][128], Ks[64][128] (xor-swizzled float4 chunks), Vs[64][128],
//       Ss[64][68].
// Thread map: tx = t&15, ty = t>>4; score tile 4x4 at (ty*4, tx*4);
// output tile 4 rows x 8 cols at (ty*4, tx*8).
// ---------------------------------------------------------------------------
#define ATTN_SMEM_FLOATS (3 * 64 * 128 + 64 * 68)
#define ATTN_SMEM_BYTES  (ATTN_SMEM_FLOATS * 4)

__global__ __launch_bounds__(256, 1) void attn_kernel(
    const float* __restrict__ Q, const float* __restrict__ K,
    const float* __restrict__ V, float* __restrict__ O)
{
    extern __shared__ float sm[];
    float*  Qs  = sm;
    float*  Ks  = Qs + 64 * 128;
    float*  Vs  = Ks + 64 * 128;
    float*  Ss  = Vs + 64 * 128;   // [64][68]
    float4* Qs4 = (float4*)Qs;
    float4* Ks4 = (float4*)Ks;
    float4* Vs4 = (float4*)Vs;

    int qt = blockIdx.x;
    int h  = blockIdx.y;
    int q0 = qt << 6;
    int t  = threadIdx.x;
    int tx = t & 15;
    int ty = t >> 4;
    int r0 = ty << 2;    // 4 score/output rows
    int c0 = tx << 2;    // 4 score cols
    int co = tx << 3;    // 8 output cols

    // Load Q tile (row-major, plain). Row stride in float4 = 512.
    {
        const float4* Qg = (const float4*)(Q + (size_t)q0 * D_MODEL + h * HEAD_DIM);
#pragma unroll
        for (int i = 0; i < 8; i++) {
            int lin = t + (i << 8);       // 0..2047
            int r   = lin >> 5;
            int d4  = lin & 31;
            Qs4[(r << 5) + d4] = Qg[(size_t)r * 512 + d4];
        }
    }

    float m[4], l[4], o[4][8];
#pragma unroll
    for (int i = 0; i < 4; i++) {
        m[i] = -1e30f;
        l[i] = 0.0f;
#pragma unroll
        for (int j = 0; j < 8; j++) o[i][j] = 0.0f;
    }

    const float scale = 0.08838834764831845f;  // 1/sqrt(128)
    const int   sw    = tx & 7;                 // K swizzle: (c>>2)&7 == tx for our cols

    for (int kt = 0; kt <= qt; kt++) {
        __syncthreads();  // previous tile fully consumed (and Qs visible on iter 0)
        {
            const float4* Kg = (const float4*)(K + ((size_t)kt << 6) * D_MODEL + h * HEAD_DIM);
            const float4* Vg = (const float4*)(V + ((size_t)kt << 6) * D_MODEL + h * HEAD_DIM);
#pragma unroll
            for (int i = 0; i < 8; i++) {
                int lin = t + (i << 8);
                int r   = lin >> 5;
                int d4  = lin & 31;
                Ks4[(r << 5) + (d4 ^ ((r >> 2) & 7))] = Kg[(size_t)r * 512 + d4];
                Vs4[(r << 5) + d4]                    = Vg[(size_t)r * 512 + d4];
            }
        }
        __syncthreads();

        // ----- scores: s[i][j] = Q[r0+i] . K[c0+j] -----
        float s[4][4];
#pragma unroll
        for (int i = 0; i < 4; i++)
#pragma unroll
            for (int j = 0; j < 4; j++) s[i][j] = 0.0f;

#pragma unroll 8
        for (int kk = 0; kk < 32; kk++) {
            float4 qv[4], kv[4];
#pragma unroll
            for (int i = 0; i < 4; i++) qv[i] = Qs4[((r0 + i) << 5) + kk];
#pragma unroll
            for (int j = 0; j < 4; j++) kv[j] = Ks4[((c0 + j) << 5) + (kk ^ sw)];
#pragma unroll
            for (int i = 0; i < 4; i++)
#pragma unroll
                for (int j = 0; j < 4; j++) {
                    s[i][j] += qv[i].x * kv[j].x;
                    s[i][j] += qv[i].y * kv[j].y;
                    s[i][j] += qv[i].z * kv[j].z;
                    s[i][j] += qv[i].w * kv[j].w;
                }
        }

        // scale + causal mask (diagonal tile only)
        bool diag = (kt == qt);
#pragma unroll
        for (int i = 0; i < 4; i++)
#pragma unroll
            for (int j = 0; j < 4; j++) {
                float sv = s[i][j] * scale;
                if (diag && (c0 + j > r0 + i)) sv = -1e30f;
                s[i][j] = sv;
            }

        // ----- online softmax (reduce across the 16 tx lanes per row) -----
        float mt[4], lt[4], alpha[4];
#pragma unroll
        for (int i = 0; i < 4; i++) {
            float v = fmaxf(fmaxf(s[i][0], s[i][1]), fmaxf(s[i][2], s[i][3]));
#pragma unroll
            for (int off = 8; off > 0; off >>= 1)
                v = fmaxf(v, __shfl_xor_sync(0xffffffffu, v, off));
            mt[i] = fmaxf(m[i], v);
            alpha[i] = __expf(m[i] - mt[i]);
        }
#pragma unroll
        for (int i = 0; i < 4; i++) {
            float sum = 0.0f;
#pragma unroll
            for (int j = 0; j < 4; j++) {
                float p = __expf(s[i][j] - mt[i]);
                s[i][j] = p;
                sum += p;
            }
#pragma unroll
            for (int off = 8; off > 0; off >>= 1)
                sum += __shfl_xor_sync(0xffffffffu, sum, off);
            l[i] = l[i] * alpha[i] + sum;
            m[i] = mt[i];
#pragma unroll
            for (int j = 0; j < 8; j++) o[i][j] *= alpha[i];
            // stash probabilities for PV phase (row owned by this warp-half)
            Ss[(r0 + i) * 68 + c0 + 0] = s[i][0];
            Ss[(r0 + i) * 68 + c0 + 1] = s[i][1];
            Ss[(r0 + i) * 68 + c0 + 2] = s[i][2];
            Ss[(r0 + i) * 68 + c0 + 3] = s[i][3];
        }
        __syncwarp();

        // ----- PV: o[i][j] += sum_k P[r0+i][k] * V[k][co+j] -----
#pragma unroll 4
        for (int k = 0; k < 64; k++) {
            float4 v0 = Vs4[(k << 5) + (co >> 2)];
            float4 v1 = Vs4[(k << 5) + (co >> 2) + 1];
#pragma unroll
            for (int i = 0; i < 4; i++) {
                float p = Ss[(r0 + i) * 68 + k];
                o[i][0] += p * v0.x;  o[i][1] += p * v0.y;
                o[i][2] += p * v0.z;  o[i][3] += p * v0.w;
                o[i][4] += p * v1.x;  o[i][5] += p * v1.y;
                o[i][6] += p * v1.z;  o[i][7] += p * v1.w;
            }
        }
    }

    // finalize + store
#pragma unroll
    for (int i = 0; i < 4; i++) {
        float inv = 1.0f / l[i];
        float* op = O + (size_t)(q0 + r0 + i) * D_MODEL + h * HEAD_DIM + co;
        *(float4*)op       = make_float4(o[i][0] * inv, o[i][1] * inv, o[i][2] * inv, o[i][3] * inv);
        *(float4*)(op + 4) = make_float4(o[i][4] * inv, o[i][5] * inv, o[i][6] * inv, o[i][7] * inv);
    }
}

// ---------------------------------------------------------------------------
extern "C" void kernel_launch(void* const* d_in, const int* in_sizes, int n_in,
                              void* d_out, int out_size)
{
    (void)in_sizes; (void)n_in; (void)out_size;
    const float* x  = (const float*)d_in[0];
    const float* fc = (const float*)d_in[1];
    const float* fs = (const float*)d_in[2];
    // d_in[3] = mask (pure causal; implemented analytically)
    const float* wq = (const float*)d_in[4];
    const float* wk = (const float*)d_in[5];
    const float* wv = (const float*)d_in[6];
    const float* wo = (const float*)d_in[7];
    float* out = (float*)d_out;

    float *Qp, *Kp, *Vp, *Ap;
    cudaGetSymbolAddress((void**)&Qp, g_Q);
    cudaGetSymbolAddress((void**)&Kp, g_K);
    cudaGetSymbolAddress((void**)&Vp, g_V);
    cudaGetSymbolAddress((void**)&Ap, g_A);

    dim3 gg(D_MODEL / 128, SEQ / 128);   // (16,16)
    sgemm_kernel<<<gg, 256>>>(x, wq, Qp);
    sgemm_kernel<<<gg, 256>>>(x, wk, Kp);
    sgemm_kernel<<<gg, 256>>>(x, wv, Vp);

    rope_kernel<<<(SEQ * (D_MODEL / 2)) / 256, 256>>>(Qp, Kp, fc, fs);

    cudaFuncSetAttribute(attn_kernel, cudaFuncAttributeMaxDynamicSharedMemorySize,
                         ATTN_SMEM_BYTES);
    attn_kernel<<<dim3(SEQ / 64, N_HEADS), 256, ATTN_SMEM_BYTES>>>(Qp, Kp, Vp, Ap);

    sgemm_kernel<<<gg, 256>>>(Ap, wo, out);
}

// round 3
// speedup vs baseline: 1.8767x; 1.8767x over previous
#include <cuda_runtime.h>
#include <cstdint>
#include <math.h>

#define D_MODEL 2048
#define SEQ     2048
#define N_HEADS 16
#define HEAD_DIM 128

// Scratch (no cudaMalloc allowed)
__device__ float g_Q[SEQ * D_MODEL];
__device__ float g_K[SEQ * D_MODEL];
__device__ float g_V[SEQ * D_MODEL];
__device__ float g_A[SEQ * D_MODEL];
__device__ float g_WT[D_MODEL * D_MODEL];

// ---------------------------------------------------------------------------
// helpers
// ---------------------------------------------------------------------------
static __device__ __forceinline__ uint32_t smem_u32(const void* p) {
    return (uint32_t)__cvta_generic_to_shared(p);
}

#define LDSM_X4(r0, r1, r2, r3, addr) \
    asm volatile("ldmatrix.sync.aligned.m8n8.x4.shared.b16 {%0,%1,%2,%3}, [%4];" \
                 : "=r"(r0), "=r"(r1), "=r"(r2), "=r"(r3) : "r"(addr))

static __device__ __forceinline__ void mma_tf32(
    float* c, const uint32_t* a, uint32_t b0, uint32_t b1)
{
    asm volatile(
        "mma.sync.aligned.m16n8k8.row.col.f32.tf32.tf32.f32 "
        "{%0,%1,%2,%3}, {%4,%5,%6,%7}, {%8,%9}, {%0,%1,%2,%3};"
        : "+f"(c[0]), "+f"(c[1]), "+f"(c[2]), "+f"(c[3])
        : "r"(a[0]), "r"(a[1]), "r"(a[2]), "r"(a[3]), "r"(b0), "r"(b1));
}

static __device__ __forceinline__ void sts_tf32x4(uint32_t addr, float4 v) {
    uint32_t a, b, c, d;
    asm("cvt.rna.tf32.f32 %0, %1;" : "=r"(a) : "f"(v.x));
    asm("cvt.rna.tf32.f32 %0, %1;" : "=r"(b) : "f"(v.y));
    asm("cvt.rna.tf32.f32 %0, %1;" : "=r"(c) : "f"(v.z));
    asm("cvt.rna.tf32.f32 %0, %1;" : "=r"(d) : "f"(v.w));
    asm volatile("st.shared.v4.b32 [%0], {%1, %2, %3, %4};"
                 :: "r"(addr), "r"(a), "r"(b), "r"(c), "r"(d) : "memory");
}

// ---------------------------------------------------------------------------
// Transpose: out[n][k] = in[k][n], 2048x2048 fp32
// ---------------------------------------------------------------------------
__global__ __launch_bounds__(256) void transpose_kernel(
    const float* __restrict__ in, float* __restrict__ out)
{
    __shared__ float tile[32][33];
    int x = blockIdx.x * 32 + threadIdx.x;
    int y = blockIdx.y * 32 + threadIdx.y;
#pragma unroll
    for (int i = 0; i < 32; i += 8)
        tile[threadIdx.y + i][threadIdx.x] = in[(size_t)(y + i) * D_MODEL + x];
    __syncthreads();
    x = blockIdx.y * 32 + threadIdx.x;
    y = blockIdx.x * 32 + threadIdx.y;
#pragma unroll
    for (int i = 0; i < 32; i += 8)
        out[(size_t)(y + i) * D_MODEL + x] = tile[threadIdx.x][threadIdx.y + i];
}

// ---------------------------------------------------------------------------
// tf32 mma.sync GEMM: C[2048,2048] = A[2048,2048] @ BT^T  (BT is [N,K] row-major)
// CTA tile 128x128, BK=32, 256 threads (8 warps, 2x4), warp tile 64x32.
// SMEM: A/B tiles stored as [128 rows][32 tf32] with 16B-chunk XOR swizzle
// (chunk ^ (row&7)) -> conflict-free ldmatrix. Double buffered (4 x 16KB).
// ---------------------------------------------------------------------------
#define GEMM_SMEM_BYTES (4 * 16384)

__global__ __launch_bounds__(256, 1) void gemm_tc_kernel(
    const float* __restrict__ A, const float* __restrict__ BT,
    float* __restrict__ C)
{
    extern __shared__ char smc[];
    uint32_t sb = smem_u32(smc);

    int t    = threadIdx.x;
    int lane = t & 31;
    int wid  = t >> 5;
    int row0 = blockIdx.y << 7;
    int col0 = blockIdx.x << 7;
    int wm   = (wid >> 2) << 6;   // 0 / 64
    int wn   = (wid & 3) << 5;    // 0 / 32 / 64 / 96

    float acc[4][4][4];
#pragma unroll
    for (int i = 0; i < 4; i++)
#pragma unroll
        for (int j = 0; j < 4; j++)
#pragma unroll
            for (int q = 0; q < 4; q++) acc[i][j][q] = 0.0f;

    // ldmatrix per-lane row / chunk-select (invariant across tiles)
    uint32_t arow  = (uint32_t)(wm + (lane & 7) + ((lane >> 3) & 1) * 8);
    uint32_t acsel = (uint32_t)((lane >> 4) & 1);
    uint32_t brow  = (uint32_t)(wn + (lane & 7) + ((lane >> 4) & 1) * 8);
    uint32_t bcsel = (uint32_t)((lane >> 3) & 1);
    uint32_t asw7  = arow & 7;
    uint32_t bsw7  = brow & 7;

    float4 ra[4], rb[4];

    // ---- prologue: load chunk 0 into buffer 0 ----
    {
        const float4* Ag = (const float4*)(A  + (size_t)row0 * D_MODEL);
        const float4* Bg = (const float4*)(BT + (size_t)col0 * D_MODEL);
#pragma unroll
        for (int i = 0; i < 4; i++) {
            int l = t + (i << 8), r = l >> 3, c4 = l & 7;
            ra[i] = Ag[(size_t)r * 512 + c4];
            rb[i] = Bg[(size_t)r * 512 + c4];
        }
#pragma unroll
        for (int i = 0; i < 4; i++) {
            int l = t + (i << 8), r = l >> 3, c4 = l & 7;
            uint32_t sw = (uint32_t)((r << 7) + ((c4 ^ (r & 7)) << 4));
            sts_tf32x4(sb + sw,         ra[i]);
            sts_tf32x4(sb + 16384 + sw, rb[i]);
        }
        __syncthreads();
    }

    const int NCHUNK = D_MODEL / 32;   // 64

    for (int c = 0; c < NCHUNK; c++) {
        int cur = c & 1;

        // prefetch chunk c+1 into registers
        if (c < NCHUNK - 1) {
            int k0 = (c + 1) << 5;
            const float4* Ag = (const float4*)(A  + (size_t)row0 * D_MODEL + k0);
            const float4* Bg = (const float4*)(BT + (size_t)col0 * D_MODEL + k0);
#pragma unroll
            for (int i = 0; i < 4; i++) {
                int l = t + (i << 8), r = l >> 3, c4 = l & 7;
                ra[i] = Ag[(size_t)r * 512 + c4];
                rb[i] = Bg[(size_t)r * 512 + c4];
            }
        }

        uint32_t ab = sb + (uint32_t)cur * 32768u;
        uint32_t bb = ab + 16384u;

#pragma unroll
        for (int s = 0; s < 4; s++) {
            uint32_t af[4][4], bf[2][4];
#pragma unroll
            for (int mt = 0; mt < 4; mt++) {
                uint32_t addr = ab + ((arow + mt * 16) << 7)
                                   + (((2u * s + acsel) ^ asw7) << 4);
                LDSM_X4(af[mt][0], af[mt][1], af[mt][2], af[mt][3], addr);
            }
#pragma unroll
            for (int p = 0; p < 2; p++) {
                uint32_t addr = bb + ((brow + p * 16) << 7)
                                   + (((2u * s + bcsel) ^ bsw7) << 4);
                LDSM_X4(bf[p][0], bf[p][1], bf[p][2], bf[p][3], addr);
            }
#pragma unroll
            for (int mt = 0; mt < 4; mt++)
#pragma unroll
                for (int nt = 0; nt < 4; nt++)
                    mma_tf32(acc[mt][nt], af[mt],
                             bf[nt >> 1][(nt & 1) * 2],
                             bf[nt >> 1][(nt & 1) * 2 + 1]);
        }

        if (c < NCHUNK - 1) {
            uint32_t nb = sb + (uint32_t)((c + 1) & 1) * 32768u;
#pragma unroll
            for (int i = 0; i < 4; i++) {
                int l = t + (i << 8), r = l >> 3, c4 = l & 7;
                uint32_t sw = (uint32_t)((r << 7) + ((c4 ^ (r & 7)) << 4));
                sts_tf32x4(nb + sw,         ra[i]);
                sts_tf32x4(nb + 16384 + sw, rb[i]);
            }
            __syncthreads();
        }
    }

    // ---- epilogue ----
#pragma unroll
    for (int mt = 0; mt < 4; mt++) {
        int re = row0 + wm + mt * 16 + (lane >> 2);
#pragma unroll
        for (int nt = 0; nt < 4; nt++) {
            int ce = col0 + wn + nt * 8 + ((lane & 3) << 1);
            *(float2*)(C + (size_t)re * D_MODEL + ce) =
                make_float2(acc[mt][nt][0], acc[mt][nt][1]);
            *(float2*)(C + (size_t)(re + 8) * D_MODEL + ce) =
                make_float2(acc[mt][nt][2], acc[mt][nt][3]);
        }
    }
}

// ---------------------------------------------------------------------------
// RoPE on Q and K in place
// ---------------------------------------------------------------------------
__global__ __launch_bounds__(256) void rope_kernel(
    float* __restrict__ Q, float* __restrict__ K,
    const float* __restrict__ fc, const float* __restrict__ fs)
{
    int idx = blockIdx.x * blockDim.x + threadIdx.x;
    int s = idx >> 10;
    int p = idx & 1023;
    int i = p & 63;
    float c  = fc[(s << 6) + i];
    float sn = fs[(s << 6) + i];
    size_t base = ((size_t)s << 11) + ((size_t)p << 1);

    float2 q = *(float2*)(Q + base);
    float2 k = *(float2*)(K + base);
    *(float2*)(Q + base) = make_float2(q.x * c - q.y * sn, q.x * sn + q.y * c);
    *(float2*)(K + base) = make_float2(k.x * c - k.y * sn, k.x * sn + k.y * c);
}

// ---------------------------------------------------------------------------
// Flash-style causal attention, fp32 (unchanged)
// ---------------------------------------------------------------------------
#define ATTN_SMEM_FLOATS (3 * 64 * 128 + 64 * 68)
#define ATTN_SMEM_BYTES  (ATTN_SMEM_FLOATS * 4)

__global__ __launch_bounds__(256, 1) void attn_kernel(
    const float* __restrict__ Q, const float* __restrict__ K,
    const float* __restrict__ V, float* __restrict__ O)
{
    extern __shared__ float smf[];
    float*  Qs  = smf;
    float*  Ks  = Qs + 64 * 128;
    float*  Vs  = Ks + 64 * 128;
    float*  Ss  = Vs + 64 * 128;   // [64][68]
    float4* Qs4 = (float4*)Qs;
    float4* Ks4 = (float4*)Ks;
    float4* Vs4 = (float4*)Vs;

    int qt = blockIdx.x;
    int h  = blockIdx.y;
    int q0 = qt << 6;
    int t  = threadIdx.x;
    int tx = t & 15;
    int ty = t >> 4;
    int r0 = ty << 2;
    int c0 = tx << 2;
    int co = tx << 3;

    {
        const float4* Qg = (const float4*)(Q + (size_t)q0 * D_MODEL + h * HEAD_DIM);
#pragma unroll
        for (int i = 0; i < 8; i++) {
            int lin = t + (i << 8);
            int r   = lin >> 5;
            int d4  = lin & 31;
            Qs4[(r << 5) + d4] = Qg[(size_t)r * 512 + d4];
        }
    }

    float m[4], l[4], o[4][8];
#pragma unroll
    for (int i = 0; i < 4; i++) {
        m[i] = -1e30f;
        l[i] = 0.0f;
#pragma unroll
        for (int j = 0; j < 8; j++) o[i][j] = 0.0f;
    }

    const float scale = 0.08838834764831845f;
    const int   sw    = tx & 7;

    for (int kt = 0; kt <= qt; kt++) {
        __syncthreads();
        {
            const float4* Kg = (const float4*)(K + ((size_t)kt << 6) * D_MODEL + h * HEAD_DIM);
            const float4* Vg = (const float4*)(V + ((size_t)kt << 6) * D_MODEL + h * HEAD_DIM);
#pragma unroll
            for (int i = 0; i < 8; i++) {
                int lin = t + (i << 8);
                int r   = lin >> 5;
                int d4  = lin & 31;
                Ks4[(r << 5) + (d4 ^ ((r >> 2) & 7))] = Kg[(size_t)r * 512 + d4];
                Vs4[(r << 5) + d4]                    = Vg[(size_t)r * 512 + d4];
            }
        }
        __syncthreads();

        float s[4][4];
#pragma unroll
        for (int i = 0; i < 4; i++)
#pragma unroll
            for (int j = 0; j < 4; j++) s[i][j] = 0.0f;

#pragma unroll 8
        for (int kk = 0; kk < 32; kk++) {
            float4 qv[4], kv[4];
#pragma unroll
            for (int i = 0; i < 4; i++) qv[i] = Qs4[((r0 + i) << 5) + kk];
#pragma unroll
            for (int j = 0; j < 4; j++) kv[j] = Ks4[((c0 + j) << 5) + (kk ^ sw)];
#pragma unroll
            for (int i = 0; i < 4; i++)
#pragma unroll
                for (int j = 0; j < 4; j++) {
                    s[i][j] += qv[i].x * kv[j].x;
                    s[i][j] += qv[i].y * kv[j].y;
                    s[i][j] += qv[i].z * kv[j].z;
                    s[i][j] += qv[i].w * kv[j].w;
                }
        }

        bool diag = (kt == qt);
#pragma unroll
        for (int i = 0; i < 4; i++)
#pragma unroll
            for (int j = 0; j < 4; j++) {
                float sv = s[i][j] * scale;
                if (diag && (c0 + j > r0 + i)) sv = -1e30f;
                s[i][j] = sv;
            }

        float mt[4], alpha[4];
#pragma unroll
        for (int i = 0; i < 4; i++) {
            float v = fmaxf(fmaxf(s[i][0], s[i][1]), fmaxf(s[i][2], s[i][3]));
#pragma unroll
            for (int off = 8; off > 0; off >>= 1)
                v = fmaxf(v, __shfl_xor_sync(0xffffffffu, v, off));
            mt[i] = fmaxf(m[i], v);
            alpha[i] = __expf(m[i] - mt[i]);
        }
#pragma unroll
        for (int i = 0; i < 4; i++) {
            float sum = 0.0f;
#pragma unroll
            for (int j = 0; j < 4; j++) {
                float p = __expf(s[i][j] - mt[i]);
                s[i][j] = p;
                sum += p;
            }
#pragma unroll
            for (int off = 8; off > 0; off >>= 1)
                sum += __shfl_xor_sync(0xffffffffu, sum, off);
            l[i] = l[i] * alpha[i] + sum;
            m[i] = mt[i];
#pragma unroll
            for (int j = 0; j < 8; j++) o[i][j] *= alpha[i];
            Ss[(r0 + i) * 68 + c0 + 0] = s[i][0];
            Ss[(r0 + i) * 68 + c0 + 1] = s[i][1];
            Ss[(r0 + i) * 68 + c0 + 2] = s[i][2];
            Ss[(r0 + i) * 68 + c0 + 3] = s[i][3];
        }
        __syncwarp();

#pragma unroll 4
        for (int k = 0; k < 64; k++) {
            float4 v0 = Vs4[(k << 5) + (co >> 2)];
            float4 v1 = Vs4[(k << 5) + (co >> 2) + 1];
#pragma unroll
            for (int i = 0; i < 4; i++) {
                float p = Ss[(r0 + i) * 68 + k];
                o[i][0] += p * v0.x;  o[i][1] += p * v0.y;
                o[i][2] += p * v0.z;  o[i][3] += p * v0.w;
                o[i][4] += p * v1.x;  o[i][5] += p * v1.y;
                o[i][6] += p * v1.z;  o[i][7] += p * v1.w;
            }
        }
    }

#pragma unroll
    for (int i = 0; i < 4; i++) {
        float inv = 1.0f / l[i];
        float* op = O + (size_t)(q0 + r0 + i) * D_MODEL + h * HEAD_DIM + co;
        *(float4*)op       = make_float4(o[i][0] * inv, o[i][1] * inv, o[i][2] * inv, o[i][3] * inv);
        *(float4*)(op + 4) = make_float4(o[i][4] * inv, o[i][5] * inv, o[i][6] * inv, o[i][7] * inv);
    }
}

// ---------------------------------------------------------------------------
extern "C" void kernel_launch(void* const* d_in, const int* in_sizes, int n_in,
                              void* d_out, int out_size)
{
    (void)in_sizes; (void)n_in; (void)out_size;
    const float* x  = (const float*)d_in[0];
    const float* fc = (const float*)d_in[1];
    const float* fs = (const float*)d_in[2];
    const float* wq = (const float*)d_in[4];
    const float* wk = (const float*)d_in[5];
    const float* wv = (const float*)d_in[6];
    const float* wo = (const float*)d_in[7];
    float* out = (float*)d_out;

    float *Qp, *Kp, *Vp, *Ap, *WTp;
    cudaGetSymbolAddress((void**)&Qp,  g_Q);
    cudaGetSymbolAddress((void**)&Kp,  g_K);
    cudaGetSymbolAddress((void**)&Vp,  g_V);
    cudaGetSymbolAddress((void**)&Ap,  g_A);
    cudaGetSymbolAddress((void**)&WTp, g_WT);

    cudaFuncSetAttribute(gemm_tc_kernel, cudaFuncAttributeMaxDynamicSharedMemorySize,
                         GEMM_SMEM_BYTES);
    cudaFuncSetAttribute(attn_kernel, cudaFuncAttributeMaxDynamicSharedMemorySize,
                         ATTN_SMEM_BYTES);

    dim3 tg(64, 64), tb(32, 8);
    dim3 gg(D_MODEL / 128, SEQ / 128);   // (16,16)

    transpose_kernel<<<tg, tb>>>(wq, WTp);
    gemm_tc_kernel<<<gg, 256, GEMM_SMEM_BYTES>>>(x, WTp, Qp);
    transpose_kernel<<<tg, tb>>>(wk, WTp);
    gemm_tc_kernel<<<gg, 256, GEMM_SMEM_BYTES>>>(x, WTp, Kp);
    transpose_kernel<<<tg, tb>>>(wv, WTp);
    gemm_tc_kernel<<<gg, 256, GEMM_SMEM_BYTES>>>(x, WTp, Vp);

    rope_kernel<<<(SEQ * (D_MODEL / 2)) / 256, 256>>>(Qp, Kp, fc, fs);

    attn_kernel<<<dim3(SEQ / 64, N_HEADS), 256, ATTN_SMEM_BYTES>>>(Qp, Kp, Vp, Ap);

    transpose_kernel<<<tg, tb>>>(wo, WTp);
    gemm_tc_kernel<<<gg, 256, GEMM_SMEM_BYTES>>>(Ap, WTp, out);
}

// round 4
// speedup vs baseline: 2.9312x; 1.5619x over previous
#include <cuda_runtime.h>
#include <cstdint>
#include <math.h>

#define D_MODEL 2048
#define SEQ     2048
#define N_HEADS 16
#define HEAD_DIM 128

// Scratch (no cudaMalloc allowed)
__device__ float g_Q[SEQ * D_MODEL];
__device__ float g_K[SEQ * D_MODEL];
__device__ float g_V[SEQ * D_MODEL];
__device__ float g_A[SEQ * D_MODEL];
__device__ float g_WT[D_MODEL * D_MODEL];

// ---------------------------------------------------------------------------
// helpers
// ---------------------------------------------------------------------------
static __device__ __forceinline__ uint32_t smem_u32(const void* p) {
    return (uint32_t)__cvta_generic_to_shared(p);
}

#define LDSM_X4(r0, r1, r2, r3, addr) \
    asm volatile("ldmatrix.sync.aligned.m8n8.x4.shared.b16 {%0,%1,%2,%3}, [%4];" \
                 : "=r"(r0), "=r"(r1), "=r"(r2), "=r"(r3) : "r"(addr))

static __device__ __forceinline__ void mma_tf32(
    float* c, const uint32_t* a, uint32_t b0, uint32_t b1)
{
    asm volatile(
        "mma.sync.aligned.m16n8k8.row.col.f32.tf32.tf32.f32 "
        "{%0,%1,%2,%3}, {%4,%5,%6,%7}, {%8,%9}, {%0,%1,%2,%3};"
        : "+f"(c[0]), "+f"(c[1]), "+f"(c[2]), "+f"(c[3])
        : "r"(a[0]), "r"(a[1]), "r"(a[2]), "r"(a[3]), "r"(b0), "r"(b1));
}

static __device__ __forceinline__ void sts_tf32x4(uint32_t addr, float4 v) {
    uint32_t a, b, c, d;
    asm("cvt.rna.tf32.f32 %0, %1;" : "=r"(a) : "f"(v.x));
    asm("cvt.rna.tf32.f32 %0, %1;" : "=r"(b) : "f"(v.y));
    asm("cvt.rna.tf32.f32 %0, %1;" : "=r"(c) : "f"(v.z));
    asm("cvt.rna.tf32.f32 %0, %1;" : "=r"(d) : "f"(v.w));
    asm volatile("st.shared.v4.b32 [%0], {%1, %2, %3, %4};"
                 :: "r"(addr), "r"(a), "r"(b), "r"(c), "r"(d) : "memory");
}

static __device__ __forceinline__ void sts_tf32(uint32_t addr, float v) {
    uint32_t a;
    asm("cvt.rna.tf32.f32 %0, %1;" : "=r"(a) : "f"(v));
    asm volatile("st.shared.b32 [%0], %1;" :: "r"(addr), "r"(a) : "memory");
}

static __device__ __forceinline__ void sts_tf32x2(uint32_t addr, float x, float y) {
    uint32_t a, b;
    asm("cvt.rna.tf32.f32 %0, %1;" : "=r"(a) : "f"(x));
    asm("cvt.rna.tf32.f32 %0, %1;" : "=r"(b) : "f"(y));
    asm volatile("st.shared.v2.b32 [%0], {%1, %2};"
                 :: "r"(addr), "r"(a), "r"(b) : "memory");
}

// ---------------------------------------------------------------------------
// Transpose: out[n][k] = in[k][n], 2048x2048 fp32
// ---------------------------------------------------------------------------
__global__ __launch_bounds__(256) void transpose_kernel(
    const float* __restrict__ in, float* __restrict__ out)
{
    __shared__ float tile[32][33];
    int x = blockIdx.x * 32 + threadIdx.x;
    int y = blockIdx.y * 32 + threadIdx.y;
#pragma unroll
    for (int i = 0; i < 32; i += 8)
        tile[threadIdx.y + i][threadIdx.x] = in[(size_t)(y + i) * D_MODEL + x];
    __syncthreads();
    x = blockIdx.y * 32 + threadIdx.x;
    y = blockIdx.x * 32 + threadIdx.y;
#pragma unroll
    for (int i = 0; i < 32; i += 8)
        out[(size_t)(y + i) * D_MODEL + x] = tile[threadIdx.x][threadIdx.y + i];
}

// ---------------------------------------------------------------------------
// tf32 mma.sync GEMM (unchanged from R3, validated)
// ---------------------------------------------------------------------------
#define GEMM_SMEM_BYTES (4 * 16384)

__global__ __launch_bounds__(256, 1) void gemm_tc_kernel(
    const float* __restrict__ A, const float* __restrict__ BT,
    float* __restrict__ C)
{
    extern __shared__ char smc[];
    uint32_t sb = smem_u32(smc);

    int t    = threadIdx.x;
    int lane = t & 31;
    int wid  = t >> 5;
    int row0 = blockIdx.y << 7;
    int col0 = blockIdx.x << 7;
    int wm   = (wid >> 2) << 6;
    int wn   = (wid & 3) << 5;

    float acc[4][4][4];
#pragma unroll
    for (int i = 0; i < 4; i++)
#pragma unroll
        for (int j = 0; j < 4; j++)
#pragma unroll
            for (int q = 0; q < 4; q++) acc[i][j][q] = 0.0f;

    uint32_t arow  = (uint32_t)(wm + (lane & 7) + ((lane >> 3) & 1) * 8);
    uint32_t acsel = (uint32_t)((lane >> 4) & 1);
    uint32_t brow  = (uint32_t)(wn + (lane & 7) + ((lane >> 4) & 1) * 8);
    uint32_t bcsel = (uint32_t)((lane >> 3) & 1);
    uint32_t asw7  = arow & 7;
    uint32_t bsw7  = brow & 7;

    float4 ra[4], rb[4];

    {
        const float4* Ag = (const float4*)(A  + (size_t)row0 * D_MODEL);
        const float4* Bg = (const float4*)(BT + (size_t)col0 * D_MODEL);
#pragma unroll
        for (int i = 0; i < 4; i++) {
            int l = t + (i << 8), r = l >> 3, c4 = l & 7;
            ra[i] = Ag[(size_t)r * 512 + c4];
            rb[i] = Bg[(size_t)r * 512 + c4];
        }
#pragma unroll
        for (int i = 0; i < 4; i++) {
            int l = t + (i << 8), r = l >> 3, c4 = l & 7;
            uint32_t sw = (uint32_t)((r << 7) + ((c4 ^ (r & 7)) << 4));
            sts_tf32x4(sb + sw,         ra[i]);
            sts_tf32x4(sb + 16384 + sw, rb[i]);
        }
        __syncthreads();
    }

    const int NCHUNK = D_MODEL / 32;

    for (int c = 0; c < NCHUNK; c++) {
        int cur = c & 1;

        if (c < NCHUNK - 1) {
            int k0 = (c + 1) << 5;
            const float4* Ag = (const float4*)(A  + (size_t)row0 * D_MODEL + k0);
            const float4* Bg = (const float4*)(BT + (size_t)col0 * D_MODEL + k0);
#pragma unroll
            for (int i = 0; i < 4; i++) {
                int l = t + (i << 8), r = l >> 3, c4 = l & 7;
                ra[i] = Ag[(size_t)r * 512 + c4];
                rb[i] = Bg[(size_t)r * 512 + c4];
            }
        }

        uint32_t ab = sb + (uint32_t)cur * 32768u;
        uint32_t bb = ab + 16384u;

#pragma unroll
        for (int s = 0; s < 4; s++) {
            uint32_t af[4][4], bf[2][4];
#pragma unroll
            for (int mt = 0; mt < 4; mt++) {
                uint32_t addr = ab + ((arow + mt * 16) << 7)
                                   + (((2u * s + acsel) ^ asw7) << 4);
                LDSM_X4(af[mt][0], af[mt][1], af[mt][2], af[mt][3], addr);
            }
#pragma unroll
            for (int p = 0; p < 2; p++) {
                uint32_t addr = bb + ((brow + p * 16) << 7)
                                   + (((2u * s + bcsel) ^ bsw7) << 4);
                LDSM_X4(bf[p][0], bf[p][1], bf[p][2], bf[p][3], addr);
            }
#pragma unroll
            for (int mt = 0; mt < 4; mt++)
#pragma unroll
                for (int nt = 0; nt < 4; nt++)
                    mma_tf32(acc[mt][nt], af[mt],
                             bf[nt >> 1][(nt & 1) * 2],
                             bf[nt >> 1][(nt & 1) * 2 + 1]);
        }

        if (c < NCHUNK - 1) {
            uint32_t nb = sb + (uint32_t)((c + 1) & 1) * 32768u;
#pragma unroll
            for (int i = 0; i < 4; i++) {
                int l = t + (i << 8), r = l >> 3, c4 = l & 7;
                uint32_t sw = (uint32_t)((r << 7) + ((c4 ^ (r & 7)) << 4));
                sts_tf32x4(nb + sw,         ra[i]);
                sts_tf32x4(nb + 16384 + sw, rb[i]);
            }
            __syncthreads();
        }
    }

#pragma unroll
    for (int mt = 0; mt < 4; mt++) {
        int re = row0 + wm + mt * 16 + (lane >> 2);
#pragma unroll
        for (int nt = 0; nt < 4; nt++) {
            int ce = col0 + wn + nt * 8 + ((lane & 3) << 1);
            *(float2*)(C + (size_t)re * D_MODEL + ce) =
                make_float2(acc[mt][nt][0], acc[mt][nt][1]);
            *(float2*)(C + (size_t)(re + 8) * D_MODEL + ce) =
                make_float2(acc[mt][nt][2], acc[mt][nt][3]);
        }
    }
}

// ---------------------------------------------------------------------------
// RoPE on Q and K in place
// ---------------------------------------------------------------------------
__global__ __launch_bounds__(256) void rope_kernel(
    float* __restrict__ Q, float* __restrict__ K,
    const float* __restrict__ fc, const float* __restrict__ fs)
{
    int idx = blockIdx.x * blockDim.x + threadIdx.x;
    int s = idx >> 10;
    int p = idx & 1023;
    int i = p & 63;
    float c  = fc[(s << 6) + i];
    float sn = fs[(s << 6) + i];
    size_t base = ((size_t)s << 11) + ((size_t)p << 1);

    float2 q = *(float2*)(Q + base);
    float2 k = *(float2*)(K + base);
    *(float2*)(Q + base) = make_float2(q.x * c - q.y * sn, q.x * sn + q.y * c);
    *(float2*)(K + base) = make_float2(k.x * c - k.y * sn, k.x * sn + k.y * c);
}

// ---------------------------------------------------------------------------
// FlashAttention-2 style causal attention on tf32 mma.sync.
// Grid: (SEQ/128, N_HEADS), 256 threads (8 warps). Warp w owns Q rows
// [w*16, w*16+16) of the 128-row Q block. KV tiles of 64 keys.
// SMEM: Ks[64][128] tf32 (pitch 512B, chunk^row&7 swizzle),
//       Vt[128][64] tf32 (V transposed, pitch 256B),
//       Ps[8 warps][16][64] tf32 (P round-trip for A-frag layout).
// ---------------------------------------------------------------------------
#define ATT_SMEM_BYTES (96 * 1024)

__global__ __launch_bounds__(256, 1) void attn_tc_kernel(
    const float* __restrict__ Q, const float* __restrict__ K,
    const float* __restrict__ V, float* __restrict__ O)
{
    extern __shared__ char smc[];
    uint32_t sb = smem_u32(smc);
    const uint32_t ks = sb;             // 32KB
    const uint32_t vt = sb + 32768;     // 32KB
    const uint32_t ps = sb + 65536;     // 32KB

    int t    = threadIdx.x;
    int lane = t & 31;
    int w    = t >> 5;
    int qt   = (int)gridDim.x - 1 - (int)blockIdx.x;   // heavy tiles first
    int h    = blockIdx.y;
    int q0   = qt << 7;

    // fragment lane geometry (matches validated GEMM patterns)
    uint32_t arow  = (uint32_t)((lane & 7) + ((lane >> 3) & 1) * 8);
    uint32_t acsel = (uint32_t)((lane >> 4) & 1);
    uint32_t brow  = (uint32_t)((lane & 7) + ((lane >> 4) & 1) * 8);
    uint32_t bcsel = (uint32_t)((lane >> 3) & 1);
    uint32_t asw   = arow & 7;
    uint32_t bsw   = brow & 7;

    // ---- stage Q (128x128) into smem (spanning ks+vt), build A-frags ----
    uint32_t qf[16][4];
    {
        const float4* Qg = (const float4*)(Q + (size_t)q0 * D_MODEL + h * HEAD_DIM);
#pragma unroll
        for (int i = 0; i < 16; i++) {
            int lin = t + (i << 8);
            int r   = lin >> 5;
            int c   = lin & 31;
            float4 v = Qg[(size_t)r * 512 + c];
            sts_tf32x4(sb + (r << 9) + (((uint32_t)c ^ (r & 7)) << 4), v);
        }
        __syncthreads();
        uint32_t qrow = arow + (uint32_t)(w << 4);
        uint32_t qsw  = qrow & 7;
#pragma unroll
        for (int s = 0; s < 16; s++) {
            uint32_t addr = sb + (qrow << 9) + (((2u * s + acsel) ^ qsw) << 4);
            LDSM_X4(qf[s][0], qf[s][1], qf[s][2], qf[s][3], addr);
        }
    }

    float oacc[16][4];
#pragma unroll
    for (int i = 0; i < 16; i++)
#pragma unroll
        for (int j = 0; j < 4; j++) oacc[i][j] = 0.0f;
    float mrow[2] = {-1e30f, -1e30f};
    float lrow[2] = {0.0f, 0.0f};

    const float scale = 0.08838834764831845f;  // 1/sqrt(128)
    const int   ktmax = 2 * qt + 1;
    const uint32_t pbase = ps + (uint32_t)(w << 12);

    for (int kt = 0; kt <= ktmax; kt++) {
        __syncthreads();   // previous K/V consumed (and Q staging done on iter 0)
        {
            const float4* Kg = (const float4*)(K + ((size_t)kt << 6) * D_MODEL + h * HEAD_DIM);
            const float4* Vg = (const float4*)(V + ((size_t)kt << 6) * D_MODEL + h * HEAD_DIM);
#pragma unroll
            for (int i = 0; i < 8; i++) {
                int lin = t + (i << 8);
                int r   = lin >> 5;      // key row 0..63
                int c   = lin & 31;      // 16B chunk
                float4 kv = Kg[(size_t)r * 512 + c];
                sts_tf32x4(ks + (r << 9) + (((uint32_t)c ^ (r & 7)) << 4), kv);
                // V transposed: Vt[d][k]
                int kk = lin & 63;       // key 0..63
                int d4 = lin >> 6;       // dim/4 0..31
                float4 vv = Vg[(size_t)kk * 512 + d4];
                uint32_t kchunk = (uint32_t)(kk >> 2);
                uint32_t koff   = (uint32_t)(kk & 3) << 2;
                int d = d4 << 2;
                sts_tf32(vt + ((d + 0) << 8) + ((kchunk ^ ((d + 0) & 7)) << 4) + koff, vv.x);
                sts_tf32(vt + ((d + 1) << 8) + ((kchunk ^ ((d + 1) & 7)) << 4) + koff, vv.y);
                sts_tf32(vt + ((d + 2) << 8) + ((kchunk ^ ((d + 2) & 7)) << 4) + koff, vv.z);
                sts_tf32(vt + ((d + 3) << 8) + ((kchunk ^ ((d + 3) & 7)) << 4) + koff, vv.w);
            }
        }
        __syncthreads();

        // ---- S = Q @ K^T : per warp m16 x n64 ----
        float sacc[8][4];
#pragma unroll
        for (int nt = 0; nt < 8; nt++)
#pragma unroll
            for (int e = 0; e < 4; e++) sacc[nt][e] = 0.0f;

#pragma unroll
        for (int s = 0; s < 16; s++) {
            uint32_t bf[4][4];
#pragma unroll
            for (int p = 0; p < 4; p++) {
                uint32_t addr = ks + ((brow + (uint32_t)(p << 4)) << 9)
                                   + (((2u * s + bcsel) ^ bsw) << 4);
                LDSM_X4(bf[p][0], bf[p][1], bf[p][2], bf[p][3], addr);
            }
#pragma unroll
            for (int nt = 0; nt < 8; nt++)
                mma_tf32(sacc[nt], qf[s],
                         bf[nt >> 1][(nt & 1) * 2],
                         bf[nt >> 1][(nt & 1) * 2 + 1]);
        }

        // ---- scale + causal mask ----
        bool need_mask = (kt >= 2 * qt);
        int grow = q0 + (w << 4) + (lane >> 2);
#pragma unroll
        for (int nt = 0; nt < 8; nt++) {
#pragma unroll
            for (int e = 0; e < 4; e++) {
                float v = sacc[nt][e] * scale;
                if (need_mask) {
                    int row = grow + (e >> 1) * 8;
                    int col = (kt << 6) + (nt << 3) + ((lane & 3) << 1) + (e & 1);
                    if (col > row) v = -1e30f;
                }
                sacc[nt][e] = v;
            }
        }

        // ---- online softmax (2 rows per thread) ----
        float alpha[2];
#pragma unroll
        for (int half = 0; half < 2; half++) {
            float mx = -1e30f;
#pragma unroll
            for (int nt = 0; nt < 8; nt++)
                mx = fmaxf(mx, fmaxf(sacc[nt][2 * half], sacc[nt][2 * half + 1]));
            mx = fmaxf(mx, __shfl_xor_sync(0xffffffffu, mx, 1));
            mx = fmaxf(mx, __shfl_xor_sync(0xffffffffu, mx, 2));
            float mnew = fmaxf(mrow[half], mx);
            alpha[half] = __expf(mrow[half] - mnew);
            float sum = 0.0f;
#pragma unroll
            for (int nt = 0; nt < 8; nt++) {
                float p0 = __expf(sacc[nt][2 * half]     - mnew);
                float p1 = __expf(sacc[nt][2 * half + 1] - mnew);
                sacc[nt][2 * half]     = p0;
                sacc[nt][2 * half + 1] = p1;
                sum += p0 + p1;
            }
            sum += __shfl_xor_sync(0xffffffffu, sum, 1);
            sum += __shfl_xor_sync(0xffffffffu, sum, 2);
            lrow[half] = lrow[half] * alpha[half] + sum;
            mrow[half] = mnew;
        }
#pragma unroll
        for (int nt = 0; nt < 16; nt++) {
            oacc[nt][0] *= alpha[0];  oacc[nt][1] *= alpha[0];
            oacc[nt][2] *= alpha[1];  oacc[nt][3] *= alpha[1];
        }

        // ---- stash P (tf32) into per-warp smem for A-frag reload ----
        {
            uint32_t prow0 = (uint32_t)(lane >> 2);
            uint32_t prow1 = prow0 + 8;
#pragma unroll
            for (int nt = 0; nt < 8; nt++) {
                uint32_t col   = (uint32_t)((nt << 3) + ((lane & 3) << 1));
                uint32_t chunk = col >> 2;
                uint32_t coff  = (col & 3) << 2;
                sts_tf32x2(pbase + (prow0 << 8) + ((chunk ^ (prow0 & 7)) << 4) + coff,
                           sacc[nt][0], sacc[nt][1]);
                sts_tf32x2(pbase + (prow1 << 8) + ((chunk ^ (prow1 & 7)) << 4) + coff,
                           sacc[nt][2], sacc[nt][3]);
            }
        }
        __syncwarp();

        // ---- O += P @ V ----
#pragma unroll
        for (int s = 0; s < 8; s++) {
            uint32_t pf[4];
            uint32_t addrA = pbase + (arow << 8) + (((2u * s + acsel) ^ asw) << 4);
            LDSM_X4(pf[0], pf[1], pf[2], pf[3], addrA);
#pragma unroll
            for (int p = 0; p < 8; p++) {
                uint32_t bvf[4];
                uint32_t addrB = vt + ((brow + (uint32_t)(p << 4)) << 8)
                                    + (((2u * s + bcsel) ^ bsw) << 4);
                LDSM_X4(bvf[0], bvf[1], bvf[2], bvf[3], addrB);
                mma_tf32(oacc[2 * p],     pf, bvf[0], bvf[1]);
                mma_tf32(oacc[2 * p + 1], pf, bvf[2], bvf[3]);
            }
        }
    }

    // ---- finalize + store ----
    float inv0 = 1.0f / lrow[0];
    float inv1 = 1.0f / lrow[1];
    int row = q0 + (w << 4) + (lane >> 2);
#pragma unroll
    for (int nt = 0; nt < 16; nt++) {
        int col = h * HEAD_DIM + (nt << 3) + ((lane & 3) << 1);
        *(float2*)(O + (size_t)row * D_MODEL + col) =
            make_float2(oacc[nt][0] * inv0, oacc[nt][1] * inv0);
        *(float2*)(O + (size_t)(row + 8) * D_MODEL + col) =
            make_float2(oacc[nt][2] * inv1, oacc[nt][3] * inv1);
    }
}

// ---------------------------------------------------------------------------
extern "C" void kernel_launch(void* const* d_in, const int* in_sizes, int n_in,
                              void* d_out, int out_size)
{
    (void)in_sizes; (void)n_in; (void)out_size;
    const float* x  = (const float*)d_in[0];
    const float* fc = (const float*)d_in[1];
    const float* fs = (const float*)d_in[2];
    const float* wq = (const float*)d_in[4];
    const float* wk = (const float*)d_in[5];
    const float* wv = (const float*)d_in[6];
    const float* wo = (const float*)d_in[7];
    float* out = (float*)d_out;

    float *Qp, *Kp, *Vp, *Ap, *WTp;
    cudaGetSymbolAddress((void**)&Qp,  g_Q);
    cudaGetSymbolAddress((void**)&Kp,  g_K);
    cudaGetSymbolAddress((void**)&Vp,  g_V);
    cudaGetSymbolAddress((void**)&Ap,  g_A);
    cudaGetSymbolAddress((void**)&WTp, g_WT);

    cudaFuncSetAttribute(gemm_tc_kernel, cudaFuncAttributeMaxDynamicSharedMemorySize,
                         GEMM_SMEM_BYTES);
    cudaFuncSetAttribute(attn_tc_kernel, cudaFuncAttributeMaxDynamicSharedMemorySize,
                         ATT_SMEM_BYTES);

    dim3 tg(64, 64), tb(32, 8);
    dim3 gg(D_MODEL / 128, SEQ / 128);

    transpose_kernel<<<tg, tb>>>(wq, WTp);
    gemm_tc_kernel<<<gg, 256, GEMM_SMEM_BYTES>>>(x, WTp, Qp);
    transpose_kernel<<<tg, tb>>>(wk, WTp);
    gemm_tc_kernel<<<gg, 256, GEMM_SMEM_BYTES>>>(x, WTp, Kp);
    transpose_kernel<<<tg, tb>>>(wv, WTp);
    gemm_tc_kernel<<<gg, 256, GEMM_SMEM_BYTES>>>(x, WTp, Vp);

    rope_kernel<<<(SEQ * (D_MODEL / 2)) / 256, 256>>>(Qp, Kp, fc, fs);

    attn_tc_kernel<<<dim3(SEQ / 128, N_HEADS), 256, ATT_SMEM_BYTES>>>(Qp, Kp, Vp, Ap);

    transpose_kernel<<<tg, tb>>>(wo, WTp);
    gemm_tc_kernel<<<gg, 256, GEMM_SMEM_BYTES>>>(Ap, WTp, out);
}

// round 5
// speedup vs baseline: 3.5099x; 1.1974x over previous
#include <cuda_runtime.h>
#include <cstdint>
#include <math.h>

#define D_MODEL 2048
#define SEQ     2048
#define N_HEADS 16
#define HEAD_DIM 128

// Scratch (no cudaMalloc allowed)
__device__ float g_Q[SEQ * D_MODEL];
__device__ float g_K[SEQ * D_MODEL];
__device__ float g_V[SEQ * D_MODEL];
__device__ float g_A[SEQ * D_MODEL];
__device__ float g_X[SEQ * D_MODEL];
__device__ float g_WT3[3 * D_MODEL * D_MODEL];

// ---------------------------------------------------------------------------
// helpers
// ---------------------------------------------------------------------------
static __device__ __forceinline__ uint32_t smem_u32(const void* p) {
    return (uint32_t)__cvta_generic_to_shared(p);
}

#define LDSM_X4(r0, r1, r2, r3, addr) \
    asm volatile("ldmatrix.sync.aligned.m8n8.x4.shared.b16 {%0,%1,%2,%3}, [%4];" \
                 : "=r"(r0), "=r"(r1), "=r"(r2), "=r"(r3) : "r"(addr))

static __device__ __forceinline__ void mma_tf32(
    float* c, const uint32_t* a, uint32_t b0, uint32_t b1)
{
    asm volatile(
        "mma.sync.aligned.m16n8k8.row.col.f32.tf32.tf32.f32 "
        "{%0,%1,%2,%3}, {%4,%5,%6,%7}, {%8,%9}, {%0,%1,%2,%3};"
        : "+f"(c[0]), "+f"(c[1]), "+f"(c[2]), "+f"(c[3])
        : "r"(a[0]), "r"(a[1]), "r"(a[2]), "r"(a[3]), "r"(b0), "r"(b1));
}

static __device__ __forceinline__ float round_tf32(float x) {
    uint32_t r;
    asm("cvt.rna.tf32.f32 %0, %1;" : "=r"(r) : "f"(x));
    return __uint_as_float(r);
}

static __device__ __forceinline__ void sts_tf32x4(uint32_t addr, float4 v) {
    uint32_t a, b, c, d;
    asm("cvt.rna.tf32.f32 %0, %1;" : "=r"(a) : "f"(v.x));
    asm("cvt.rna.tf32.f32 %0, %1;" : "=r"(b) : "f"(v.y));
    asm("cvt.rna.tf32.f32 %0, %1;" : "=r"(c) : "f"(v.z));
    asm("cvt.rna.tf32.f32 %0, %1;" : "=r"(d) : "f"(v.w));
    asm volatile("st.shared.v4.b32 [%0], {%1, %2, %3, %4};"
                 :: "r"(addr), "r"(a), "r"(b), "r"(c), "r"(d) : "memory");
}

static __device__ __forceinline__ void sts_tf32(uint32_t addr, float v) {
    uint32_t a;
    asm("cvt.rna.tf32.f32 %0, %1;" : "=r"(a) : "f"(v));
    asm volatile("st.shared.b32 [%0], %1;" :: "r"(addr), "r"(a) : "memory");
}

static __device__ __forceinline__ void sts_tf32x2(uint32_t addr, float x, float y) {
    uint32_t a, b;
    asm("cvt.rna.tf32.f32 %0, %1;" : "=r"(a) : "f"(x));
    asm("cvt.rna.tf32.f32 %0, %1;" : "=r"(b) : "f"(y));
    asm volatile("st.shared.v2.b32 [%0], {%1, %2};"
                 :: "r"(addr), "r"(a), "r"(b) : "memory");
}

static __device__ __forceinline__ void cp_async16(uint32_t dst, const void* src) {
    asm volatile("cp.async.cg.shared.global [%0], [%1], 16;"
                 :: "r"(dst), "l"(src) : "memory");
}
#define CP_COMMIT() asm volatile("cp.async.commit_group;" ::: "memory")

// ---------------------------------------------------------------------------
// Round-copy x -> tf32-rounded copy
// ---------------------------------------------------------------------------
__global__ __launch_bounds__(256) void round_kernel(
    const float* __restrict__ in, float* __restrict__ out)
{
    int i = blockIdx.x * blockDim.x + threadIdx.x;
    float4 v = ((const float4*)in)[i];
    v.x = round_tf32(v.x); v.y = round_tf32(v.y);
    v.z = round_tf32(v.z); v.w = round_tf32(v.w);
    ((float4*)out)[i] = v;
}

// ---------------------------------------------------------------------------
// Transpose + tf32 round: out[n][k] = tf32(in[k][n]), 2048x2048 fp32
// ---------------------------------------------------------------------------
__global__ __launch_bounds__(256) void transpose_kernel(
    const float* __restrict__ in, float* __restrict__ out)
{
    __shared__ float tile[32][33];
    int x = blockIdx.x * 32 + threadIdx.x;
    int y = blockIdx.y * 32 + threadIdx.y;
#pragma unroll
    for (int i = 0; i < 32; i += 8)
        tile[threadIdx.y + i][threadIdx.x] = in[(size_t)(y + i) * D_MODEL + x];
    __syncthreads();
    x = blockIdx.y * 32 + threadIdx.x;
    y = blockIdx.x * 32 + threadIdx.y;
#pragma unroll
    for (int i = 0; i < 32; i += 8)
        out[(size_t)(y + i) * D_MODEL + x] = round_tf32(tile[threadIdx.x][threadIdx.y + i]);
}

// ---------------------------------------------------------------------------
// tf32 mma.sync GEMM with 3-stage cp.async pipeline.
// Inputs MUST be pre-rounded to tf32 (raw byte copies into smem).
// C_sel[2048,128-slab] = A[2048,2048] @ BT_slab^T, BT is [gridDim.x*128, 2048].
// blockIdx.x selects 128 BT rows; mat = bx>>4 selects output C0/C1/C2.
// ---------------------------------------------------------------------------
#define GSTAGES 3
#define GEMM_SMEM_BYTES (GSTAGES * 32768)

__global__ __launch_bounds__(256, 2) void gemm_tc_kernel(
    const float* __restrict__ A, const float* __restrict__ BT,
    float* __restrict__ C0, float* __restrict__ C1, float* __restrict__ C2)
{
    extern __shared__ char smc[];
    uint32_t sb = smem_u32(smc);

    int t    = threadIdx.x;
    int lane = t & 31;
    int wid  = t >> 5;
    int row0 = blockIdx.y << 7;
    int bx   = blockIdx.x;
    int mat  = bx >> 4;
    int col0 = (bx & 15) << 7;
    float* C = (mat == 0) ? C0 : (mat == 1 ? C1 : C2);
    const float* Arow = A + (size_t)row0 * D_MODEL;
    const float* Brow = BT + ((size_t)bx << 7) * D_MODEL;

    int wm = (wid >> 2) << 6;
    int wn = (wid & 3) << 5;

    float acc[4][4][4];
#pragma unroll
    for (int i = 0; i < 4; i++)
#pragma unroll
        for (int j = 0; j < 4; j++)
#pragma unroll
            for (int q = 0; q < 4; q++) acc[i][j][q] = 0.0f;

    uint32_t arow  = (uint32_t)(wm + (lane & 7) + ((lane >> 3) & 1) * 8);
    uint32_t acsel = (uint32_t)((lane >> 4) & 1);
    uint32_t brow  = (uint32_t)(wn + (lane & 7) + ((lane >> 4) & 1) * 8);
    uint32_t bcsel = (uint32_t)((lane >> 3) & 1);
    uint32_t asw7  = arow & 7;
    uint32_t bsw7  = brow & 7;

    // per-thread copy geometry (2 rows x 1 chunk per 256-thread pass, 4 passes)
    const int cr  = t >> 3;         // row 0..31 base
    const int cc  = t & 7;          // chunk 0..7
    const uint32_t csw = (uint32_t)((cr << 7) + ((cc ^ (cr & 7)) << 4));

    const int NCHUNK = D_MODEL / 32;   // 64

    // prologue: stage 0 and 1
#pragma unroll
    for (int pc = 0; pc < 2; pc++) {
        uint32_t buf = sb + (uint32_t)pc * 32768u;
        const float* Ag = Arow + (pc << 5);
        const float* Bg = Brow + (pc << 5);
#pragma unroll
        for (int i = 0; i < 4; i++) {
            uint32_t d = buf + csw + (uint32_t)(i << 12);   // +32 rows = 32*128B
            const float* as = Ag + (size_t)(cr + (i << 5)) * D_MODEL + (cc << 2);
            const float* bs = Bg + (size_t)(cr + (i << 5)) * D_MODEL + (cc << 2);
            cp_async16(d, as);
            cp_async16(d + 16384, bs);
        }
        CP_COMMIT();
    }

    int stage = 0;
#pragma unroll 1
    for (int c = 0; c < NCHUNK; c++) {
        if (c + 1 < NCHUNK) asm volatile("cp.async.wait_group 1;" ::: "memory");
        else                asm volatile("cp.async.wait_group 0;" ::: "memory");
        __syncthreads();

        uint32_t ab = sb + (uint32_t)stage * 32768u;
        uint32_t bb = ab + 16384u;

#pragma unroll
        for (int s = 0; s < 4; s++) {
            uint32_t af[4][4], bf[2][4];
#pragma unroll
            for (int mt = 0; mt < 4; mt++) {
                uint32_t addr = ab + ((arow + mt * 16) << 7)
                                   + (((2u * s + acsel) ^ asw7) << 4);
                LDSM_X4(af[mt][0], af[mt][1], af[mt][2], af[mt][3], addr);
            }
#pragma unroll
            for (int p = 0; p < 2; p++) {
                uint32_t addr = bb + ((brow + p * 16) << 7)
                                   + (((2u * s + bcsel) ^ bsw7) << 4);
                LDSM_X4(bf[p][0], bf[p][1], bf[p][2], bf[p][3], addr);
            }
#pragma unroll
            for (int mt = 0; mt < 4; mt++)
#pragma unroll
                for (int nt = 0; nt < 4; nt++)
                    mma_tf32(acc[mt][nt], af[mt],
                             bf[nt >> 1][(nt & 1) * 2],
                             bf[nt >> 1][(nt & 1) * 2 + 1]);
        }

        __syncthreads();

        if (c + 2 < NCHUNK) {
            int nc = c + 2;
            uint32_t buf = sb + (uint32_t)((stage + 2) % GSTAGES) * 32768u;
            const float* Ag = Arow + (nc << 5);
            const float* Bg = Brow + (nc << 5);
#pragma unroll
            for (int i = 0; i < 4; i++) {
                uint32_t d = buf + csw + (uint32_t)(i << 12);
                const float* as = Ag + (size_t)(cr + (i << 5)) * D_MODEL + (cc << 2);
                const float* bs = Bg + (size_t)(cr + (i << 5)) * D_MODEL + (cc << 2);
                cp_async16(d, as);
                cp_async16(d + 16384, bs);
            }
        }
        CP_COMMIT();   // commit every iter (possibly empty) to keep group count fixed

        stage++;
        if (stage == GSTAGES) stage = 0;
    }

    // ---- epilogue ----
#pragma unroll
    for (int mt = 0; mt < 4; mt++) {
        int re = row0 + wm + mt * 16 + (lane >> 2);
#pragma unroll
        for (int nt = 0; nt < 4; nt++) {
            int ce = col0 + wn + nt * 8 + ((lane & 3) << 1);
            *(float2*)(C + (size_t)re * D_MODEL + ce) =
                make_float2(acc[mt][nt][0], acc[mt][nt][1]);
            *(float2*)(C + (size_t)(re + 8) * D_MODEL + ce) =
                make_float2(acc[mt][nt][2], acc[mt][nt][3]);
        }
    }
}

// ---------------------------------------------------------------------------
// RoPE on Q and K in place
// ---------------------------------------------------------------------------
__global__ __launch_bounds__(256) void rope_kernel(
    float* __restrict__ Q, float* __restrict__ K,
    const float* __restrict__ fc, const float* __restrict__ fs)
{
    int idx = blockIdx.x * blockDim.x + threadIdx.x;
    int s = idx >> 10;
    int p = idx & 1023;
    int i = p & 63;
    float c  = fc[(s << 6) + i];
    float sn = fs[(s << 6) + i];
    size_t base = ((size_t)s << 11) + ((size_t)p << 1);

    float2 q = *(float2*)(Q + base);
    float2 k = *(float2*)(K + base);
    *(float2*)(Q + base) = make_float2(q.x * c - q.y * sn, q.x * sn + q.y * c);
    *(float2*)(K + base) = make_float2(k.x * c - k.y * sn, k.x * sn + k.y * c);
}

// ---------------------------------------------------------------------------
// FlashAttention-2 style causal attention on tf32 mma.sync (validated R4).
// Epilogue now rounds output to tf32 (feeds raw-copy GEMM).
// ---------------------------------------------------------------------------
#define ATT_SMEM_BYTES (96 * 1024)

__global__ __launch_bounds__(256, 1) void attn_tc_kernel(
    const float* __restrict__ Q, const float* __restrict__ K,
    const float* __restrict__ V, float* __restrict__ O)
{
    extern __shared__ char smc[];
    uint32_t sb = smem_u32(smc);
    const uint32_t ks = sb;
    const uint32_t vt = sb + 32768;
    const uint32_t ps = sb + 65536;

    int t    = threadIdx.x;
    int lane = t & 31;
    int w    = t >> 5;
    int qt   = (int)gridDim.x - 1 - (int)blockIdx.x;
    int h    = blockIdx.y;
    int q0   = qt << 7;

    uint32_t arow  = (uint32_t)((lane & 7) + ((lane >> 3) & 1) * 8);
    uint32_t acsel = (uint32_t)((lane >> 4) & 1);
    uint32_t brow  = (uint32_t)((lane & 7) + ((lane >> 4) & 1) * 8);
    uint32_t bcsel = (uint32_t)((lane >> 3) & 1);
    uint32_t asw   = arow & 7;
    uint32_t bsw   = brow & 7;

    uint32_t qf[16][4];
    {
        const float4* Qg = (const float4*)(Q + (size_t)q0 * D_MODEL + h * HEAD_DIM);
#pragma unroll
        for (int i = 0; i < 16; i++) {
            int lin = t + (i << 8);
            int r   = lin >> 5;
            int c   = lin & 31;
            float4 v = Qg[(size_t)r * 512 + c];
            sts_tf32x4(sb + (r << 9) + (((uint32_t)c ^ (r & 7)) << 4), v);
        }
        __syncthreads();
        uint32_t qrow = arow + (uint32_t)(w << 4);
        uint32_t qsw  = qrow & 7;
#pragma unroll
        for (int s = 0; s < 16; s++) {
            uint32_t addr = sb + (qrow << 9) + (((2u * s + acsel) ^ qsw) << 4);
            LDSM_X4(qf[s][0], qf[s][1], qf[s][2], qf[s][3], addr);
        }
    }

    float oacc[16][4];
#pragma unroll
    for (int i = 0; i < 16; i++)
#pragma unroll
        for (int j = 0; j < 4; j++) oacc[i][j] = 0.0f;
    float mrow[2] = {-1e30f, -1e30f};
    float lrow[2] = {0.0f, 0.0f};

    const float scale = 0.08838834764831845f;
    const int   ktmax = 2 * qt + 1;
    const uint32_t pbase = ps + (uint32_t)(w << 12);

    for (int kt = 0; kt <= ktmax; kt++) {
        __syncthreads();
        {
            const float4* Kg = (const float4*)(K + ((size_t)kt << 6) * D_MODEL + h * HEAD_DIM);
            const float4* Vg = (const float4*)(V + ((size_t)kt << 6) * D_MODEL + h * HEAD_DIM);
#pragma unroll
            for (int i = 0; i < 8; i++) {
                int lin = t + (i << 8);
                int r   = lin >> 5;
                int c   = lin & 31;
                float4 kv = Kg[(size_t)r * 512 + c];
                sts_tf32x4(ks + (r << 9) + (((uint32_t)c ^ (r & 7)) << 4), kv);
                int kk = lin & 63;
                int d4 = lin >> 6;
                float4 vv = Vg[(size_t)kk * 512 + d4];
                uint32_t kchunk = (uint32_t)(kk >> 2);
                uint32_t koff   = (uint32_t)(kk & 3) << 2;
                int d = d4 << 2;
                sts_tf32(vt + ((d + 0) << 8) + ((kchunk ^ ((d + 0) & 7)) << 4) + koff, vv.x);
                sts_tf32(vt + ((d + 1) << 8) + ((kchunk ^ ((d + 1) & 7)) << 4) + koff, vv.y);
                sts_tf32(vt + ((d + 2) << 8) + ((kchunk ^ ((d + 2) & 7)) << 4) + koff, vv.z);
                sts_tf32(vt + ((d + 3) << 8) + ((kchunk ^ ((d + 3) & 7)) << 4) + koff, vv.w);
            }
        }
        __syncthreads();

        float sacc[8][4];
#pragma unroll
        for (int nt = 0; nt < 8; nt++)
#pragma unroll
            for (int e = 0; e < 4; e++) sacc[nt][e] = 0.0f;

#pragma unroll
        for (int s = 0; s < 16; s++) {
            uint32_t bf[4][4];
#pragma unroll
            for (int p = 0; p < 4; p++) {
                uint32_t addr = ks + ((brow + (uint32_t)(p << 4)) << 9)
                                   + (((2u * s + bcsel) ^ bsw) << 4);
                LDSM_X4(bf[p][0], bf[p][1], bf[p][2], bf[p][3], addr);
            }
#pragma unroll
            for (int nt = 0; nt < 8; nt++)
                mma_tf32(sacc[nt], qf[s],
                         bf[nt >> 1][(nt & 1) * 2],
                         bf[nt >> 1][(nt & 1) * 2 + 1]);
        }

        bool need_mask = (kt >= 2 * qt);
        int grow = q0 + (w << 4) + (lane >> 2);
#pragma unroll
        for (int nt = 0; nt < 8; nt++) {
#pragma unroll
            for (int e = 0; e < 4; e++) {
                float v = sacc[nt][e] * scale;
                if (need_mask) {
                    int row = grow + (e >> 1) * 8;
                    int col = (kt << 6) + (nt << 3) + ((lane & 3) << 1) + (e & 1);
                    if (col > row) v = -1e30f;
                }
                sacc[nt][e] = v;
            }
        }

        float alpha[2];
#pragma unroll
        for (int half = 0; half < 2; half++) {
            float mx = -1e30f;
#pragma unroll
            for (int nt = 0; nt < 8; nt++)
                mx = fmaxf(mx, fmaxf(sacc[nt][2 * half], sacc[nt][2 * half + 1]));
            mx = fmaxf(mx, __shfl_xor_sync(0xffffffffu, mx, 1));
            mx = fmaxf(mx, __shfl_xor_sync(0xffffffffu, mx, 2));
            float mnew = fmaxf(mrow[half], mx);
            alpha[half] = __expf(mrow[half] - mnew);
            float sum = 0.0f;
#pragma unroll
            for (int nt = 0; nt < 8; nt++) {
                float p0 = __expf(sacc[nt][2 * half]     - mnew);
                float p1 = __expf(sacc[nt][2 * half + 1] - mnew);
                sacc[nt][2 * half]     = p0;
                sacc[nt][2 * half + 1] = p1;
                sum += p0 + p1;
            }
            sum += __shfl_xor_sync(0xffffffffu, sum, 1);
            sum += __shfl_xor_sync(0xffffffffu, sum, 2);
            lrow[half] = lrow[half] * alpha[half] + sum;
            mrow[half] = mnew;
        }
#pragma unroll
        for (int nt = 0; nt < 16; nt++) {
            oacc[nt][0] *= alpha[0];  oacc[nt][1] *= alpha[0];
            oacc[nt][2] *= alpha[1];  oacc[nt][3] *= alpha[1];
        }

        {
            uint32_t prow0 = (uint32_t)(lane >> 2);
            uint32_t prow1 = prow0 + 8;
#pragma unroll
            for (int nt = 0; nt < 8; nt++) {
                uint32_t col   = (uint32_t)((nt << 3) + ((lane & 3) << 1));
                uint32_t chunk = col >> 2;
                uint32_t coff  = (col & 3) << 2;
                sts_tf32x2(pbase + (prow0 << 8) + ((chunk ^ (prow0 & 7)) << 4) + coff,
                           sacc[nt][0], sacc[nt][1]);
                sts_tf32x2(pbase + (prow1 << 8) + ((chunk ^ (prow1 & 7)) << 4) + coff,
                           sacc[nt][2], sacc[nt][3]);
            }
        }
        __syncwarp();

#pragma unroll
        for (int s = 0; s < 8; s++) {
            uint32_t pf[4];
            uint32_t addrA = pbase + (arow << 8) + (((2u * s + acsel) ^ asw) << 4);
            LDSM_X4(pf[0], pf[1], pf[2], pf[3], addrA);
#pragma unroll
            for (int p = 0; p < 8; p++) {
                uint32_t bvf[4];
                uint32_t addrB = vt + ((brow + (uint32_t)(p << 4)) << 8)
                                    + (((2u * s + bcsel) ^ bsw) << 4);
                LDSM_X4(bvf[0], bvf[1], bvf[2], bvf[3], addrB);
                mma_tf32(oacc[2 * p],     pf, bvf[0], bvf[1]);
                mma_tf32(oacc[2 * p + 1], pf, bvf[2], bvf[3]);
            }
        }
    }

    float inv0 = 1.0f / lrow[0];
    float inv1 = 1.0f / lrow[1];
    int row = q0 + (w << 4) + (lane >> 2);
#pragma unroll
    for (int nt = 0; nt < 16; nt++) {
        int col = h * HEAD_DIM + (nt << 3) + ((lane & 3) << 1);
        *(float2*)(O + (size_t)row * D_MODEL + col) =
            make_float2(round_tf32(oacc[nt][0] * inv0), round_tf32(oacc[nt][1] * inv0));
        *(float2*)(O + (size_t)(row + 8) * D_MODEL + col) =
            make_float2(round_tf32(oacc[nt][2] * inv1), round_tf32(oacc[nt][3] * inv1));
    }
}

// ---------------------------------------------------------------------------
extern "C" void kernel_launch(void* const* d_in, const int* in_sizes, int n_in,
                              void* d_out, int out_size)
{
    (void)in_sizes; (void)n_in; (void)out_size;
    const float* x  = (const float*)d_in[0];
    const float* fc = (const float*)d_in[1];
    const float* fs = (const float*)d_in[2];
    const float* wq = (const float*)d_in[4];
    const float* wk = (const float*)d_in[5];
    const float* wv = (const float*)d_in[6];
    const float* wo = (const float*)d_in[7];
    float* out = (float*)d_out;

    float *Qp, *Kp, *Vp, *Ap, *Xp, *WT3p;
    cudaGetSymbolAddress((void**)&Qp,   g_Q);
    cudaGetSymbolAddress((void**)&Kp,   g_K);
    cudaGetSymbolAddress((void**)&Vp,   g_V);
    cudaGetSymbolAddress((void**)&Ap,   g_A);
    cudaGetSymbolAddress((void**)&Xp,   g_X);
    cudaGetSymbolAddress((void**)&WT3p, g_WT3);

    cudaFuncSetAttribute(gemm_tc_kernel, cudaFuncAttributeMaxDynamicSharedMemorySize,
                         GEMM_SMEM_BYTES);
    cudaFuncSetAttribute(attn_tc_kernel, cudaFuncAttributeMaxDynamicSharedMemorySize,
                         ATT_SMEM_BYTES);

    dim3 tg(64, 64), tb(32, 8);
    const size_t WSZ = (size_t)D_MODEL * D_MODEL;

    // pre-round x; transpose+round weights (QKV concatenated)
    round_kernel<<<(SEQ * D_MODEL) / (256 * 4), 256>>>(x, Xp);
    transpose_kernel<<<tg, tb>>>(wq, WT3p);
    transpose_kernel<<<tg, tb>>>(wk, WT3p + WSZ);
    transpose_kernel<<<tg, tb>>>(wv, WT3p + 2 * WSZ);

    // fused QKV GEMM: grid (48,16)
    gemm_tc_kernel<<<dim3(48, 16), 256, GEMM_SMEM_BYTES>>>(Xp, WT3p, Qp, Kp, Vp);

    rope_kernel<<<(SEQ * (D_MODEL / 2)) / 256, 256>>>(Qp, Kp, fc, fs);

    attn_tc_kernel<<<dim3(SEQ / 128, N_HEADS), 256, ATT_SMEM_BYTES>>>(Qp, Kp, Vp, Ap);

    // output projection
    transpose_kernel<<<tg, tb>>>(wo, WT3p);
    gemm_tc_kernel<<<dim3(16, 16), 256, GEMM_SMEM_BYTES>>>(Ap, WT3p, out, out, out);
}